// round 7
// baseline (speedup 1.0000x reference)
#include <cuda_runtime.h>
#include <math.h>
#include <stdint.h>

#define D_DIM 1024
#define H_DIM 1024
#define E_DIM 64
#define M_TOTAL 65536

#if defined(__CUDA_ARCH__) && (__CUDA_ARCH__ >= 1000) && \
    (defined(__CUDA_ARCH_FEAT_SM103_ALL) || defined(__CUDA_ARCH_FEAT_SM100_ALL) || \
     defined(__CUDA_ARCH_SPECIFIC__) || defined(__CUDA_ARCH_FAMILY_SPECIFIC__))
#define HAS_TCGEN05 1
#else
#define HAS_TCGEN05 0
#endif

// ---------------- static device scratch -------------------------------------
__device__ float g_Hhi[(size_t)M_TOTAL * H_DIM];   // 256 MB
__device__ float g_Hlo[(size_t)M_TOTAL * H_DIM];   // 256 MB
__device__ float g_xhi[(size_t)M_TOTAL * D_DIM];   // 256 MB
__device__ float g_xlo[(size_t)M_TOTAL * D_DIM];   // 256 MB
__device__ float g_w1hi[H_DIM * D_DIM];            // 4 MB
__device__ float g_w1lo[H_DIM * D_DIM];            // 4 MB
__device__ float g_w2hi[E_DIM * H_DIM];            // 256 KB
__device__ float g_w2lo[E_DIM * H_DIM];            // 256 KB

// ---------------- PTX helpers ------------------------------------------------
__device__ __forceinline__ uint32_t smem_u32(const void* p) {
    uint32_t a;
    asm("{ .reg .u64 t; cvta.to.shared.u64 t, %1; cvt.u32.u64 %0, t; }"
        : "=r"(a) : "l"(p));
    return a;
}

#define SWZ128(o) ((o) ^ (((o) >> 3) & 0x70))

__device__ __forceinline__ void mbar_init(uint32_t mbar, uint32_t cnt) {
    asm volatile("mbarrier.init.shared.b64 [%0], %1;" :: "r"(mbar), "r"(cnt) : "memory");
}
__device__ __forceinline__ void mbar_wait(uint32_t mbar, uint32_t parity) {
    asm volatile(
        "{\n\t"
        ".reg .pred P;\n\t"
        "WL%=:\n\t"
        "mbarrier.try_wait.parity.shared::cta.b64 P, [%0], %1, 0x989680;\n\t"
        "@P bra WD%=;\n\t"
        "bra WL%=;\n\t"
        "WD%=:\n\t"
        "}"
        :: "r"(mbar), "r"(parity) : "memory");
}
__device__ __forceinline__ void mbar_arrive(uint32_t mbar) {
    asm volatile("mbarrier.arrive.shared.b64 _, [%0];" :: "r"(mbar) : "memory");
}
__device__ __forceinline__ void fence_proxy_async_cta() {
    asm volatile("fence.proxy.async.shared::cta;" ::: "memory");
}
__device__ __forceinline__ void cp_async16(uint32_t dst, const void* src) {
    asm volatile("cp.async.cg.shared.global [%0], [%1], 16;"
                 :: "r"(dst), "l"(src) : "memory");
}
__device__ __forceinline__ void cp_async_commit() {
    asm volatile("cp.async.commit_group;" ::: "memory");
}
__device__ __forceinline__ void cp_async_wait0() {
    asm volatile("cp.async.wait_group 0;" ::: "memory");
}

__device__ __forceinline__ float tf32_rnd(float a) {
    uint32_t r;
    asm("cvt.rna.tf32.f32 %0, %1;" : "=r"(r) : "f"(a));
    return __uint_as_float(r);
}
__device__ __forceinline__ void split4(float4 v, float4& h, float4& l) {
    h.x = tf32_rnd(v.x); l.x = tf32_rnd(v.x - h.x);
    h.y = tf32_rnd(v.y); l.y = tf32_rnd(v.y - h.y);
    h.z = tf32_rnd(v.z); l.z = tf32_rnd(v.z - h.z);
    h.w = tf32_rnd(v.w); l.w = tf32_rnd(v.w - h.w);
}

#if HAS_TCGEN05
__device__ __forceinline__ uint64_t make_desc_sw128(uint32_t addr) {
    const uint64_t base = (2ull << 61) | (1ull << 46) | (64ull << 32) | (1ull << 16);
    return base | ((uint64_t)(addr >> 4) & 0x3FFF);
}
__device__ __forceinline__ void mma_tf32_ss(uint32_t d_tmem, uint64_t a_desc,
                                            uint64_t b_desc, uint32_t idesc,
                                            uint32_t enable_d) {
    asm volatile(
        "{\n\t"
        ".reg .pred p;\n\t"
        "setp.ne.u32 p, %5, 0;\n\t"
        "tcgen05.mma.cta_group::1.kind::tf32 [%0], %1, %2, %3, {%4, %4, %4, %4}, p;\n\t"
        "}"
        :: "r"(d_tmem), "l"(a_desc), "l"(b_desc), "r"(idesc), "r"(0u), "r"(enable_d)
        : "memory");
}
__device__ __forceinline__ void tc_commit(uint32_t mbar) {
    asm volatile(
        "tcgen05.commit.cta_group::1.mbarrier::arrive::one.shared::cluster.b64 [%0];"
        :: "r"(mbar) : "memory");
}
__device__ __forceinline__ void tc_alloc(uint32_t slot, uint32_t ncols) {
    asm volatile("tcgen05.alloc.cta_group::1.sync.aligned.shared::cta.b32 [%0], %1;"
                 :: "r"(slot), "r"(ncols) : "memory");
}
__device__ __forceinline__ void tc_dealloc(uint32_t tmem, uint32_t ncols) {
    asm volatile("tcgen05.relinquish_alloc_permit.cta_group::1.sync.aligned;");
    asm volatile("tcgen05.dealloc.cta_group::1.sync.aligned.b32 %0, %1;" :: "r"(tmem), "r"(ncols));
}
__device__ __forceinline__ void tc_fence_after() {
    asm volatile("tcgen05.fence::after_thread_sync;" ::: "memory");
}
__device__ __forceinline__ void tc_wait_ld() {
    asm volatile("tcgen05.wait::ld.sync.aligned;" ::: "memory");
}

#define TC_LD_X32(r, a)                                                       \
    asm volatile(                                                             \
        "tcgen05.ld.sync.aligned.32x32b.x32.b32 "                             \
        "{%0, %1, %2, %3, %4, %5, %6, %7, "                                   \
        " %8, %9, %10, %11, %12, %13, %14, %15, "                             \
        " %16, %17, %18, %19, %20, %21, %22, %23, "                           \
        " %24, %25, %26, %27, %28, %29, %30, %31}, [%32];"                    \
        : "=r"((r)[0]),  "=r"((r)[1]),  "=r"((r)[2]),  "=r"((r)[3]),          \
          "=r"((r)[4]),  "=r"((r)[5]),  "=r"((r)[6]),  "=r"((r)[7]),          \
          "=r"((r)[8]),  "=r"((r)[9]),  "=r"((r)[10]), "=r"((r)[11]),         \
          "=r"((r)[12]), "=r"((r)[13]), "=r"((r)[14]), "=r"((r)[15]),         \
          "=r"((r)[16]), "=r"((r)[17]), "=r"((r)[18]), "=r"((r)[19]),         \
          "=r"((r)[20]), "=r"((r)[21]), "=r"((r)[22]), "=r"((r)[23]),         \
          "=r"((r)[24]), "=r"((r)[25]), "=r"((r)[26]), "=r"((r)[27]),         \
          "=r"((r)[28]), "=r"((r)[29]), "=r"((r)[30]), "=r"((r)[31])          \
        : "r"(a))
#endif  // HAS_TCGEN05

// ---------------- split f32 -> tf32 hi/lo ------------------------------------
__global__ void split_tf32_kernel(const float4* __restrict__ src,
                                  float4* __restrict__ hi,
                                  float4* __restrict__ lo, int n4) {
    int i = blockIdx.x * blockDim.x + threadIdx.x;
    if (i >= n4) return;
    float4 v = src[i];
    float4 h, l;
    split4(v, h, l);
    hi[i] = h;
    lo[i] = l;
}

// ============================================================================
// GEMM1: H = gelu(x @ W1^T + b1). 3xTF32, cp.async producers, presplit inputs.
// BM=128, BN=256, BK=32, 2 stages, 288 threads.
// ============================================================================
#define BK 32
#define NIT (D_DIM / BK)
#define STAGE_BYTES 98304
#define OFF_ALO 16384
#define OFF_BHI 32768
#define OFF_BLO 65536
#define GEMM1_SMEM (1024 + 2 * STAGE_BYTES)

#define IDESC_G1 ((1u << 4) | (2u << 7) | (2u << 10) | ((256u / 8) << 17) | ((128u / 16) << 24))

extern "C" __global__ void __launch_bounds__(288, 1) gemm1_kernel(
    const float* __restrict__ x,   const float* __restrict__ W1,
    const float* __restrict__ xhi, const float* __restrict__ xlo,
    const float* __restrict__ whi, const float* __restrict__ wlo,
    const float* __restrict__ b1,
    float* __restrict__ Hhi, float* __restrict__ Hlo)
{
    extern __shared__ __align__(1024) char smem[];
    const int tid = threadIdx.x;
    const int bm = blockIdx.y * 128;

#if HAS_TCGEN05
    (void)x; (void)W1;
    const uint32_t sbase = smem_u32(smem);
    const int bn = blockIdx.x * 256;

    if (tid == 0) {
#pragma unroll
        for (int s = 0; s < 2; s++) {
            mbar_init(sbase + 64 + 16 * s, 256);     // full
            mbar_init(sbase + 64 + 16 * s + 8, 1);   // empty
        }
    }
    if (tid >= 256) tc_alloc(sbase, 256);
    __syncthreads();

    uint32_t tmem_base;
    asm volatile("ld.shared.b32 %0, [%1];" : "=r"(tmem_base) : "r"(sbase));

    if (tid < 256) {
        // ---------------- producers: pure cp.async ---------------------------
        const int r0 = tid >> 3;
        const int c4 = tid & 7;
        uint32_t offA[4], offB[8];
#pragma unroll
        for (int j = 0; j < 4; j++)
            offA[j] = SWZ128((uint32_t)(r0 + 32 * j) * 128 + c4 * 16);
#pragma unroll
        for (int j = 0; j < 8; j++)
            offB[j] = SWZ128((uint32_t)(r0 + 32 * j) * 128 + c4 * 16);

        const float* pAh = xhi + (size_t)(bm + r0) * D_DIM + c4 * 4;
        const float* pAl = xlo + (size_t)(bm + r0) * D_DIM + c4 * 4;
        const float* pBh = whi + (size_t)(bn + r0) * D_DIM + c4 * 4;
        const float* pBl = wlo + (size_t)(bn + r0) * D_DIM + c4 * 4;

        uint32_t pe0 = 1, pe1 = 1;

        for (int ii = 0; ii < NIT / 2; ii++) {
#pragma unroll
            for (int s = 0; s < 2; s++) {
                const int i = ii * 2 + s;
                const uint32_t mb_full  = sbase + 64 + 16 * s;
                const uint32_t mb_empty = mb_full + 8;
                if (s == 0) { mbar_wait(mb_empty, pe0); pe0 ^= 1; }
                else        { mbar_wait(mb_empty, pe1); pe1 ^= 1; }

                const int k0 = i * BK;
                const uint32_t st = sbase + 1024 + s * STAGE_BYTES;
#pragma unroll
                for (int j = 0; j < 4; j++) {
                    cp_async16(st + offA[j],           pAh + (size_t)(32 * j) * D_DIM + k0);
                    cp_async16(st + OFF_ALO + offA[j], pAl + (size_t)(32 * j) * D_DIM + k0);
                }
#pragma unroll
                for (int j = 0; j < 8; j++) {
                    cp_async16(st + OFF_BHI + offB[j], pBh + (size_t)(32 * j) * D_DIM + k0);
                    cp_async16(st + OFF_BLO + offB[j], pBl + (size_t)(32 * j) * D_DIM + k0);
                }
                cp_async_commit();
                cp_async_wait0();
                fence_proxy_async_cta();
                mbar_arrive(mb_full);
            }
        }

        mbar_wait(sbase + 64 + 8, pe0);
        mbar_wait(sbase + 64 + 16 + 8, pe1);
        tc_fence_after();

        // ---------------- epilogue: bias + gelu + hi/lo store ----------------
        const int w = tid >> 5, lane = tid & 31;
        const int colbase = (w >> 2) * 128;
        const int row = bm + (w & 3) * 32 + lane;
        float* hirow = Hhi + (size_t)row * H_DIM + bn + colbase;
        float* lorow = Hlo + (size_t)row * H_DIM + bn + colbase;
        const float* brow = b1 + bn + colbase;
#pragma unroll
        for (int ch = 0; ch < 4; ch++) {
            uint32_t r[32];
            TC_LD_X32(r, tmem_base + colbase + ch * 32);
            tc_wait_ld();
#pragma unroll
            for (int q = 0; q < 8; q++) {
                float4 bias = *(const float4*)(brow + ch * 32 + q * 4);
                float v0 = __uint_as_float(r[q * 4 + 0]) + bias.x;
                float v1 = __uint_as_float(r[q * 4 + 1]) + bias.y;
                float v2 = __uint_as_float(r[q * 4 + 2]) + bias.z;
                float v3 = __uint_as_float(r[q * 4 + 3]) + bias.w;
                float4 o;
                o.x = 0.5f * v0 * (1.0f + erff(v0 * 0.7071067811865476f));
                o.y = 0.5f * v1 * (1.0f + erff(v1 * 0.7071067811865476f));
                o.z = 0.5f * v2 * (1.0f + erff(v2 * 0.7071067811865476f));
                o.w = 0.5f * v3 * (1.0f + erff(v3 * 0.7071067811865476f));
                float4 h, l; split4(o, h, l);
                *(float4*)(hirow + ch * 32 + q * 4) = h;
                *(float4*)(lorow + ch * 32 + q * 4) = l;
            }
        }
    } else if (tid == 256) {
        // ---------------- MMA issuer ----------------------------------------
        uint32_t pf0 = 0, pf1 = 0;
        for (int ii = 0; ii < NIT / 2; ii++) {
#pragma unroll
            for (int s = 0; s < 2; s++) {
                const int i = ii * 2 + s;
                const uint32_t mb_full  = sbase + 64 + 16 * s;
                const uint32_t mb_empty = mb_full + 8;
                if (s == 0) { mbar_wait(mb_full, pf0); pf0 ^= 1; }
                else        { mbar_wait(mb_full, pf1); pf1 ^= 1; }

                uint32_t sb = sbase + 1024 + s * STAGE_BYTES;
                uint64_t dAh = make_desc_sw128(sb);
                uint64_t dAl = make_desc_sw128(sb + OFF_ALO);
                uint64_t dBh = make_desc_sw128(sb + OFF_BHI);
                uint64_t dBl = make_desc_sw128(sb + OFF_BLO);
#pragma unroll
                for (int ks = 0; ks < 4; ks++) {
                    mma_tf32_ss(tmem_base, dAh + 2 * ks, dBh + 2 * ks, IDESC_G1,
                                (i == 0 && ks == 0) ? 0u : 1u);
                    mma_tf32_ss(tmem_base, dAh + 2 * ks, dBl + 2 * ks, IDESC_G1, 1u);
                    mma_tf32_ss(tmem_base, dAl + 2 * ks, dBh + 2 * ks, IDESC_G1, 1u);
                }
                tc_commit(mb_empty);
            }
        }
    }

    __syncthreads();
    if (tid >= 256) tc_dealloc(tmem_base, 256);

#else  // ---------- FFMA fallback (generic pass) -----------------------------
    (void)xhi; (void)xlo; (void)whi; (void)wlo;
    float* As = (float*)smem;
    float* Bs = As + 8 * 128;

    const int tx = tid & 15;
    const int ty = tid >> 4;
    const int lr = tid >> 1;
    const int lc = (tid & 1) * 4;

    for (int half = 0; half < 2; half++) {
        const int bn = blockIdx.x * 256 + half * 128;
        float acc[8][8];
#pragma unroll
        for (int i = 0; i < 8; i++)
#pragma unroll
            for (int j = 0; j < 8; j++) acc[i][j] = 0.0f;

        for (int k0 = 0; k0 < D_DIM; k0 += 8) {
            __syncthreads();
            if (tid < 256) {
                float4 a4 = *(const float4*)(x  + (size_t)(bm + lr) * D_DIM + lc + k0);
                float4 b4 = *(const float4*)(W1 + (size_t)(bn + lr) * D_DIM + lc + k0);
                As[(lc + 0) * 128 + lr] = a4.x; As[(lc + 1) * 128 + lr] = a4.y;
                As[(lc + 2) * 128 + lr] = a4.z; As[(lc + 3) * 128 + lr] = a4.w;
                Bs[(lc + 0) * 128 + lr] = b4.x; Bs[(lc + 1) * 128 + lr] = b4.y;
                Bs[(lc + 2) * 128 + lr] = b4.z; Bs[(lc + 3) * 128 + lr] = b4.w;
            }
            __syncthreads();
            if (tid < 256) {
#pragma unroll
                for (int kk = 0; kk < 8; kk++) {
                    float a[8], b[8];
                    *(float4*)(a)     = *(const float4*)&As[kk * 128 + ty * 8];
                    *(float4*)(a + 4) = *(const float4*)&As[kk * 128 + ty * 8 + 4];
                    *(float4*)(b)     = *(const float4*)&Bs[kk * 128 + tx * 8];
                    *(float4*)(b + 4) = *(const float4*)&Bs[kk * 128 + tx * 8 + 4];
#pragma unroll
                    for (int i = 0; i < 8; i++)
#pragma unroll
                        for (int j = 0; j < 8; j++)
                            acc[i][j] = fmaf(a[i], b[j], acc[i][j]);
                }
            }
        }

        if (tid < 256) {
            float bias[8];
            *(float4*)(bias)     = *(const float4*)&b1[bn + tx * 8];
            *(float4*)(bias + 4) = *(const float4*)&b1[bn + tx * 8 + 4];
#pragma unroll
            for (int i = 0; i < 8; i++) {
                const int row = bm + ty * 8 + i;
                float o[8];
#pragma unroll
                for (int j = 0; j < 8; j++) {
                    float v = acc[i][j] + bias[j];
                    o[j] = 0.5f * v * (1.0f + erff(v * 0.7071067811865476f));
                }
                float4 h0, l0, h1, l1;
                split4(make_float4(o[0], o[1], o[2], o[3]), h0, l0);
                split4(make_float4(o[4], o[5], o[6], o[7]), h1, l1);
                float* dh = Hhi + (size_t)row * H_DIM + bn + tx * 8;
                float* dl = Hlo + (size_t)row * H_DIM + bn + tx * 8;
                *(float4*)(dh)     = h0; *(float4*)(dh + 4) = h1;
                *(float4*)(dl)     = l0; *(float4*)(dl + 4) = l1;
            }
        }
        __syncthreads();
    }
#endif
}

// ============================================================================
// GEMM2: logits = (H @ W2^T + b2)/temp; top-2 softmax. cp.async + presplit.
// BM=128, BN=64, BK=32, 4 stages, 288 threads.
// ============================================================================
#define NIT2 (H_DIM / 32)
#define STAGE2_BYTES 49152
#define OFF2_HLO 16384
#define OFF2_WHI 32768
#define OFF2_WLO 40960
#define GEMM2_SMEM (1024 + 4 * STAGE2_BYTES)

#define IDESC_G2 ((1u << 4) | (2u << 7) | (2u << 10) | ((64u / 8) << 17) | ((128u / 16) << 24))

extern "C" __global__ void __launch_bounds__(288, 1) gemm2_kernel(
    const float* __restrict__ Hhi, const float* __restrict__ Hlo,
    const float* __restrict__ w2hi, const float* __restrict__ w2lo,
    const float* __restrict__ b2, const float* __restrict__ log_temp,
    float* __restrict__ out)
{
    extern __shared__ __align__(1024) char smem[];
    const int tid = threadIdx.x;
    const int bm = blockIdx.x * 128;

#if HAS_TCGEN05
    const uint32_t sbase = smem_u32(smem);

    if (tid == 0) {
#pragma unroll
        for (int s = 0; s < 4; s++) {
            mbar_init(sbase + 64 + 16 * s, 256);
            mbar_init(sbase + 64 + 16 * s + 8, 1);
        }
    }
    if (tid >= 256) tc_alloc(sbase, 64);
    __syncthreads();

    uint32_t tmem_base;
    asm volatile("ld.shared.b32 %0, [%1];" : "=r"(tmem_base) : "r"(sbase));

    if (tid < 256) {
        const int r0 = tid >> 3;
        const int c4 = tid & 7;
        uint32_t offH[4], offW[2];
#pragma unroll
        for (int j = 0; j < 4; j++)
            offH[j] = SWZ128((uint32_t)(r0 + 32 * j) * 128 + c4 * 16);
#pragma unroll
        for (int j = 0; j < 2; j++)
            offW[j] = SWZ128((uint32_t)(r0 + 32 * j) * 128 + c4 * 16);

        const float* pHh = Hhi  + (size_t)(bm + r0) * H_DIM + c4 * 4;
        const float* pHl = Hlo  + (size_t)(bm + r0) * H_DIM + c4 * 4;
        const float* pWh = w2hi + (size_t)r0 * H_DIM + c4 * 4;
        const float* pWl = w2lo + (size_t)r0 * H_DIM + c4 * 4;

        uint32_t pe[4] = {1, 1, 1, 1};

        for (int ii = 0; ii < NIT2 / 4; ii++) {
#pragma unroll
            for (int s = 0; s < 4; s++) {
                const int i = ii * 4 + s;
                const uint32_t mb_full  = sbase + 64 + 16 * s;
                const uint32_t mb_empty = mb_full + 8;
                mbar_wait(mb_empty, pe[s]); pe[s] ^= 1;

                const int k0 = i * 32;
                const uint32_t st = sbase + 1024 + s * STAGE2_BYTES;
#pragma unroll
                for (int j = 0; j < 4; j++) {
                    cp_async16(st + offH[j],            pHh + (size_t)(32 * j) * H_DIM + k0);
                    cp_async16(st + OFF2_HLO + offH[j], pHl + (size_t)(32 * j) * H_DIM + k0);
                }
#pragma unroll
                for (int j = 0; j < 2; j++) {
                    cp_async16(st + OFF2_WHI + offW[j], pWh + (size_t)(32 * j) * H_DIM + k0);
                    cp_async16(st + OFF2_WLO + offW[j], pWl + (size_t)(32 * j) * H_DIM + k0);
                }
                cp_async_commit();
                cp_async_wait0();
                fence_proxy_async_cta();
                mbar_arrive(mb_full);
            }
        }

#pragma unroll
        for (int s = 0; s < 4; s++)
            mbar_wait(sbase + 64 + 16 * s + 8, pe[s]);
        tc_fence_after();
    } else if (tid == 256) {
        uint32_t pf[4] = {0, 0, 0, 0};
        for (int ii = 0; ii < NIT2 / 4; ii++) {
#pragma unroll
            for (int s = 0; s < 4; s++) {
                const int i = ii * 4 + s;
                const uint32_t mb_full  = sbase + 64 + 16 * s;
                const uint32_t mb_empty = mb_full + 8;
                mbar_wait(mb_full, pf[s]); pf[s] ^= 1;

                uint32_t sb = sbase + 1024 + s * STAGE2_BYTES;
                uint64_t dHh = make_desc_sw128(sb);
                uint64_t dHl = make_desc_sw128(sb + OFF2_HLO);
                uint64_t dWh = make_desc_sw128(sb + OFF2_WHI);
                uint64_t dWl = make_desc_sw128(sb + OFF2_WLO);
#pragma unroll
                for (int ks = 0; ks < 4; ks++) {
                    mma_tf32_ss(tmem_base, dHh + 2 * ks, dWh + 2 * ks, IDESC_G2,
                                (i == 0 && ks == 0) ? 0u : 1u);
                    mma_tf32_ss(tmem_base, dHh + 2 * ks, dWl + 2 * ks, IDESC_G2, 1u);
                    mma_tf32_ss(tmem_base, dHl + 2 * ks, dWh + 2 * ks, IDESC_G2, 1u);
                }
                tc_commit(mb_empty);
            }
        }
    }
    __syncthreads();

    float* Ls  = (float*)(smem + 1024);            // [128][65]
    float* p1s = (float*)(smem + 1024 + 33280);
    float* p2s = p1s + 128;
    int*   i1s = (int*)(p2s + 128);
    int*   i2s = i1s + 128;

    float t = expf(*log_temp);
    t = fminf(fmaxf(t, 1e-3f), 100.0f);
    const float it = 1.0f / t;

    if (tid < 256) {
        const int w = tid >> 5, lane = tid & 31;
        const int row = (w & 3) * 32 + lane;
        const int colbase = (w >> 2) * 32;
        uint32_t r[32];
        TC_LD_X32(r, tmem_base + colbase);
        tc_wait_ld();
#pragma unroll
        for (int c = 0; c < 32; c++)
            Ls[row * 65 + colbase + c] =
                (__uint_as_float(r[c]) + b2[colbase + c]) * it;
    }
    __syncthreads();

    if (tid < 128) {
        float m1 = -INFINITY, m2 = -INFINITY;
        int i1 = -1, i2 = -1;
#pragma unroll 8
        for (int e = 0; e < E_DIM; e++) {
            float v = Ls[tid * 65 + e];
            if (v > m1) { m2 = m1; i2 = i1; m1 = v; i1 = e; }
            else if (v > m2) { m2 = v; i2 = e; }
        }
        float ed = expf(m2 - m1);
        float s = 1.0f / (1.0f + ed);
        p1s[tid] = s;
        p2s[tid] = ed * s;
        i1s[tid] = i1;
        i2s[tid] = i2;
    }
    __syncthreads();

    if (tid < 256) {
        for (int idx = tid; idx < 128 * E_DIM; idx += 256) {
            const int r = idx >> 6;
            const int e = idx & 63;
            float v = 0.0f;
            if (e == i1s[r]) v = p1s[r];
            else if (e == i2s[r]) v = p2s[r];
            out[(size_t)(bm + r) * E_DIM + e] = v;
        }
    }

    __syncthreads();
    if (tid >= 256) tc_dealloc(tmem_base, 64);

#else  // ---------- FFMA fallback (generic pass) -----------------------------
    (void)w2hi; (void)w2lo;
    float* Hs  = (float*)smem;
    float* Ws  = Hs + 16 * 128;
    float* Ls  = Ws + 16 * 64;
    float* p1s = Ls + 128 * 65;
    float* p2s = p1s + 128;
    int*   i1s = (int*)(p2s + 128);
    int*   i2s = i1s + 128;

    const int tx = tid & 15;
    const int ty = tid >> 4;
    const int hr0 = tid >> 2;
    const int hc0 = (tid & 3) * 4;
    const int hr1 = (tid + 256) >> 2;
    const int wr = tid >> 2;
    const int wc = (tid & 3) * 4;

    float acc[8][4];
#pragma unroll
    for (int i = 0; i < 8; i++)
#pragma unroll
        for (int j = 0; j < 4; j++) acc[i][j] = 0.0f;

    for (int k0 = 0; k0 < H_DIM; k0 += 16) {
        __syncthreads();
        if (tid < 256) {
            float4 h0h = *(const float4*)(Hhi + (size_t)(bm + hr0) * H_DIM + k0 + hc0);
            float4 h0l = *(const float4*)(Hlo + (size_t)(bm + hr0) * H_DIM + k0 + hc0);
            float4 h1h = *(const float4*)(Hhi + (size_t)(bm + hr1) * H_DIM + k0 + hc0);
            float4 h1l = *(const float4*)(Hlo + (size_t)(bm + hr1) * H_DIM + k0 + hc0);
            float4 w4h = *(const float4*)(w2hi + (size_t)wr * H_DIM + k0 + wc);
            float4 w4l = *(const float4*)(w2lo + (size_t)wr * H_DIM + k0 + wc);
            Hs[(hc0 + 0) * 128 + hr0] = h0h.x + h0l.x; Hs[(hc0 + 1) * 128 + hr0] = h0h.y + h0l.y;
            Hs[(hc0 + 2) * 128 + hr0] = h0h.z + h0l.z; Hs[(hc0 + 3) * 128 + hr0] = h0h.w + h0l.w;
            Hs[(hc0 + 0) * 128 + hr1] = h1h.x + h1l.x; Hs[(hc0 + 1) * 128 + hr1] = h1h.y + h1l.y;
            Hs[(hc0 + 2) * 128 + hr1] = h1h.z + h1l.z; Hs[(hc0 + 3) * 128 + hr1] = h1h.w + h1l.w;
            Ws[(wc + 0) * 64 + wr] = w4h.x + w4l.x; Ws[(wc + 1) * 64 + wr] = w4h.y + w4l.y;
            Ws[(wc + 2) * 64 + wr] = w4h.z + w4l.z; Ws[(wc + 3) * 64 + wr] = w4h.w + w4l.w;
        }
        __syncthreads();
        if (tid < 256) {
#pragma unroll
            for (int kk = 0; kk < 16; kk++) {
                float a[8], b[4];
                *(float4*)(a)     = *(const float4*)&Hs[kk * 128 + ty * 8];
                *(float4*)(a + 4) = *(const float4*)&Hs[kk * 128 + ty * 8 + 4];
                *(float4*)(b)     = *(const float4*)&Ws[kk * 64 + tx * 4];
#pragma unroll
                for (int i = 0; i < 8; i++)
#pragma unroll
                    for (int j = 0; j < 4; j++)
                        acc[i][j] = fmaf(a[i], b[j], acc[i][j]);
            }
        }
    }

    float t = expf(*log_temp);
    t = fminf(fmaxf(t, 1e-3f), 100.0f);
    const float it = 1.0f / t;

    if (tid < 256) {
#pragma unroll
        for (int i = 0; i < 8; i++)
#pragma unroll
            for (int j = 0; j < 4; j++) {
                const int col = tx * 4 + j;
                Ls[(ty * 8 + i) * 65 + col] = (acc[i][j] + b2[col]) * it;
            }
    }
    __syncthreads();

    if (tid < 128) {
        float m1 = -INFINITY, m2 = -INFINITY;
        int i1 = -1, i2 = -1;
#pragma unroll 8
        for (int e = 0; e < E_DIM; e++) {
            float v = Ls[tid * 65 + e];
            if (v > m1) { m2 = m1; i2 = i1; m1 = v; i1 = e; }
            else if (v > m2) { m2 = v; i2 = e; }
        }
        float ed = expf(m2 - m1);
        float s = 1.0f / (1.0f + ed);
        p1s[tid] = s;
        p2s[tid] = ed * s;
        i1s[tid] = i1;
        i2s[tid] = i2;
    }
    __syncthreads();

    if (tid < 256) {
        for (int idx = tid; idx < 128 * E_DIM; idx += 256) {
            const int r = idx >> 6;
            const int e = idx & 63;
            float v = 0.0f;
            if (e == i1s[r]) v = p1s[r];
            else if (e == i2s[r]) v = p2s[r];
            out[(size_t)(bm + r) * E_DIM + e] = v;
        }
    }
#endif
}

// ---------------- launcher ---------------------------------------------------
extern "C" void kernel_launch(void* const* d_in, const int* in_sizes, int n_in,
                              void* d_out, int out_size) {
    const float* x  = (const float*)d_in[0];
    const float* W1 = (const float*)d_in[1];
    const float* b1 = (const float*)d_in[2];
    const float* W2 = (const float*)d_in[3];
    const float* b2 = (const float*)d_in[4];
    const float* lt = (const float*)d_in[5];
    float* out = (float*)d_out;

    const int M = in_sizes[0] / D_DIM;   // 65536

    float *Hhi, *Hlo, *xhi, *xlo, *w1hi, *w1lo, *w2hi, *w2lo;
    cudaGetSymbolAddress((void**)&Hhi, g_Hhi);
    cudaGetSymbolAddress((void**)&Hlo, g_Hlo);
    cudaGetSymbolAddress((void**)&xhi, g_xhi);
    cudaGetSymbolAddress((void**)&xlo, g_xlo);
    cudaGetSymbolAddress((void**)&w1hi, g_w1hi);
    cudaGetSymbolAddress((void**)&w1lo, g_w1lo);
    cudaGetSymbolAddress((void**)&w2hi, g_w2hi);
    cudaGetSymbolAddress((void**)&w2lo, g_w2lo);

    static int smem_set = 0;
    if (!smem_set) {
        cudaFuncSetAttribute(gemm1_kernel,
                             cudaFuncAttributeMaxDynamicSharedMemorySize, GEMM1_SMEM);
        cudaFuncSetAttribute(gemm2_kernel,
                             cudaFuncAttributeMaxDynamicSharedMemorySize, GEMM2_SMEM);
        smem_set = 1;
    }

    // presplit x, W1, W2
    {
        int n4x = M * D_DIM / 4;
        split_tf32_kernel<<<n4x / 256, 256>>>((const float4*)x, (float4*)xhi,
                                              (float4*)xlo, n4x);
        int n4w1 = H_DIM * D_DIM / 4;
        split_tf32_kernel<<<n4w1 / 256, 256>>>((const float4*)W1, (float4*)w1hi,
                                               (float4*)w1lo, n4w1);
        int n4w2 = E_DIM * H_DIM / 4;
        split_tf32_kernel<<<n4w2 / 256, 256>>>((const float4*)W2, (float4*)w2hi,
                                               (float4*)w2lo, n4w2);
    }

    dim3 grid1(H_DIM / 256, M / 128);
    gemm1_kernel<<<grid1, 288, GEMM1_SMEM>>>(x, W1, xhi, xlo, w1hi, w1lo, b1,
                                             Hhi, Hlo);

    dim3 grid2(M / 128);
    gemm2_kernel<<<grid2, 288, GEMM2_SMEM>>>(Hhi, Hlo, w2hi, w2lo, b2, lt, out);
}

// round 8
// speedup vs baseline: 1.2424x; 1.2424x over previous
#include <cuda_runtime.h>
#include <math.h>
#include <stdint.h>

#define D_DIM 1024
#define H_DIM 1024
#define E_DIM 64
#define M_TOTAL 65536
#define G1_TILES ((M_TOTAL / 128) * (H_DIM / 256))   // 2048

#if defined(__CUDA_ARCH__) && (__CUDA_ARCH__ >= 1000) && \
    (defined(__CUDA_ARCH_FEAT_SM103_ALL) || defined(__CUDA_ARCH_FEAT_SM100_ALL) || \
     defined(__CUDA_ARCH_SPECIFIC__) || defined(__CUDA_ARCH_FAMILY_SPECIFIC__))
#define HAS_TCGEN05 1
#else
#define HAS_TCGEN05 0
#endif

__device__ float g_H[(size_t)M_TOTAL * H_DIM];   // 256 MB hidden activations

// ---------------- PTX helpers ------------------------------------------------
__device__ __forceinline__ uint32_t smem_u32(const void* p) {
    uint32_t a;
    asm("{ .reg .u64 t; cvta.to.shared.u64 t, %1; cvt.u32.u64 %0, t; }"
        : "=r"(a) : "l"(p));
    return a;
}

#define SWZ128(o) ((o) ^ (((o) >> 3) & 0x70))

__device__ __forceinline__ void mbar_init(uint32_t mbar, uint32_t cnt) {
    asm volatile("mbarrier.init.shared.b64 [%0], %1;" :: "r"(mbar), "r"(cnt) : "memory");
}
__device__ __forceinline__ void mbar_wait(uint32_t mbar, uint32_t parity) {
    asm volatile(
        "{\n\t"
        ".reg .pred P;\n\t"
        "WL%=:\n\t"
        "mbarrier.try_wait.parity.shared::cta.b64 P, [%0], %1, 0x989680;\n\t"
        "@P bra WD%=;\n\t"
        "bra WL%=;\n\t"
        "WD%=:\n\t"
        "}"
        :: "r"(mbar), "r"(parity) : "memory");
}
__device__ __forceinline__ void mbar_arrive(uint32_t mbar) {
    asm volatile("mbarrier.arrive.shared.b64 _, [%0];" :: "r"(mbar) : "memory");
}
__device__ __forceinline__ void fence_proxy_async_cta() {
    asm volatile("fence.proxy.async.shared::cta;" ::: "memory");
}

__device__ __forceinline__ float tf32_rnd(float a) {
    uint32_t r;
    asm("cvt.rna.tf32.f32 %0, %1;" : "=r"(r) : "f"(a));
    return __uint_as_float(r);
}
__device__ __forceinline__ void split4(float4 v, float4& h, float4& l) {
    h.x = tf32_rnd(v.x); l.x = tf32_rnd(v.x - h.x);
    h.y = tf32_rnd(v.y); l.y = tf32_rnd(v.y - h.y);
    h.z = tf32_rnd(v.z); l.z = tf32_rnd(v.z - h.z);
    h.w = tf32_rnd(v.w); l.w = tf32_rnd(v.w - h.w);
}

#if HAS_TCGEN05
__device__ __forceinline__ uint64_t make_desc_sw128(uint32_t addr) {
    const uint64_t base = (2ull << 61) | (1ull << 46) | (64ull << 32) | (1ull << 16);
    return base | ((uint64_t)(addr >> 4) & 0x3FFF);
}
__device__ __forceinline__ void mma_tf32_ss(uint32_t d_tmem, uint64_t a_desc,
                                            uint64_t b_desc, uint32_t idesc,
                                            uint32_t enable_d) {
    asm volatile(
        "{\n\t"
        ".reg .pred p;\n\t"
        "setp.ne.u32 p, %5, 0;\n\t"
        "tcgen05.mma.cta_group::1.kind::tf32 [%0], %1, %2, %3, {%4, %4, %4, %4}, p;\n\t"
        "}"
        :: "r"(d_tmem), "l"(a_desc), "l"(b_desc), "r"(idesc), "r"(0u), "r"(enable_d)
        : "memory");
}
__device__ __forceinline__ void tc_commit(uint32_t mbar) {
    asm volatile(
        "tcgen05.commit.cta_group::1.mbarrier::arrive::one.shared::cluster.b64 [%0];"
        :: "r"(mbar) : "memory");
}
__device__ __forceinline__ void tc_alloc(uint32_t slot, uint32_t ncols) {
    asm volatile("tcgen05.alloc.cta_group::1.sync.aligned.shared::cta.b32 [%0], %1;"
                 :: "r"(slot), "r"(ncols) : "memory");
}
__device__ __forceinline__ void tc_dealloc(uint32_t tmem, uint32_t ncols) {
    asm volatile("tcgen05.relinquish_alloc_permit.cta_group::1.sync.aligned;");
    asm volatile("tcgen05.dealloc.cta_group::1.sync.aligned.b32 %0, %1;" :: "r"(tmem), "r"(ncols));
}
__device__ __forceinline__ void tc_fence_after() {
    asm volatile("tcgen05.fence::after_thread_sync;" ::: "memory");
}
__device__ __forceinline__ void tc_fence_before() {
    asm volatile("tcgen05.fence::before_thread_sync;" ::: "memory");
}
__device__ __forceinline__ void tc_wait_ld() {
    asm volatile("tcgen05.wait::ld.sync.aligned;" ::: "memory");
}

#define TC_LD_X32(r, a)                                                       \
    asm volatile(                                                             \
        "tcgen05.ld.sync.aligned.32x32b.x32.b32 "                             \
        "{%0, %1, %2, %3, %4, %5, %6, %7, "                                   \
        " %8, %9, %10, %11, %12, %13, %14, %15, "                             \
        " %16, %17, %18, %19, %20, %21, %22, %23, "                           \
        " %24, %25, %26, %27, %28, %29, %30, %31}, [%32];"                    \
        : "=r"((r)[0]),  "=r"((r)[1]),  "=r"((r)[2]),  "=r"((r)[3]),          \
          "=r"((r)[4]),  "=r"((r)[5]),  "=r"((r)[6]),  "=r"((r)[7]),          \
          "=r"((r)[8]),  "=r"((r)[9]),  "=r"((r)[10]), "=r"((r)[11]),         \
          "=r"((r)[12]), "=r"((r)[13]), "=r"((r)[14]), "=r"((r)[15]),         \
          "=r"((r)[16]), "=r"((r)[17]), "=r"((r)[18]), "=r"((r)[19]),         \
          "=r"((r)[20]), "=r"((r)[21]), "=r"((r)[22]), "=r"((r)[23]),         \
          "=r"((r)[24]), "=r"((r)[25]), "=r"((r)[26]), "=r"((r)[27]),         \
          "=r"((r)[28]), "=r"((r)[29]), "=r"((r)[30]), "=r"((r)[31])          \
        : "r"(a))
#endif  // HAS_TCGEN05

__device__ __forceinline__ float gelu_erf(float v) {
    return 0.5f * v * (1.0f + erff(v * 0.7071067811865476f));
}

// ============================================================================
// GEMM1 (persistent): H = gelu(x @ W1^T + b1). 3xTF32, in-register split.
// BM=128, BN=256, BK=32, 2-stage ring. 416 thr: 256 prod | warp8 MMA | 4 epi.
// TMEM: two 256-col D buffers, alternating per tile.
// ============================================================================
#define BK 32
#define NIT (D_DIM / BK)
#define STAGE_BYTES 98304
#define OFF_ALO 16384
#define OFF_BHI 32768
#define OFF_BLO 65536
#define GEMM1_SMEM (1024 + 2 * STAGE_BYTES)

#define IDESC_G1 ((1u << 4) | (2u << 7) | (2u << 10) | ((256u / 8) << 17) | ((128u / 16) << 24))

extern "C" __global__ void __launch_bounds__(416, 1) gemm1_kernel(
    const float* __restrict__ x, const float* __restrict__ W1,
    const float* __restrict__ b1, float* __restrict__ Hout)
{
    extern __shared__ __align__(1024) char smem[];
    const int tid = threadIdx.x;

#if HAS_TCGEN05
    const uint32_t sbase = smem_u32(smem);
    // mbars: full[s]=64+16s, empty[s]=72+16s, tdone[b]=96+16b, dfree[b]=104+16b
    if (tid == 0) {
#pragma unroll
        for (int s = 0; s < 2; s++) {
            mbar_init(sbase + 64 + 16 * s, 256);       // full
            mbar_init(sbase + 64 + 16 * s + 8, 1);     // empty (MMA commit)
            mbar_init(sbase + 96 + 16 * s, 1);         // tdone (MMA commit)
            mbar_init(sbase + 96 + 16 * s + 8, 128);   // dfree (epilogue)
        }
    }
    if (tid >= 256 && tid < 288) tc_alloc(sbase, 512);
    __syncthreads();

    uint32_t tmem_base;
    asm volatile("ld.shared.b32 %0, [%1];" : "=r"(tmem_base) : "r"(sbase));

    if (tid < 256) {
        // ---------------- producers: LDG f32 + register split + STS ----------
        const int r0 = tid >> 3;
        const int c4 = tid & 7;
        uint32_t offA[4], offB[8];
#pragma unroll
        for (int j = 0; j < 4; j++)
            offA[j] = SWZ128((uint32_t)(r0 + 32 * j) * 128 + c4 * 16);
#pragma unroll
        for (int j = 0; j < 8; j++)
            offB[j] = SWZ128((uint32_t)(r0 + 32 * j) * 128 + c4 * 16);

        uint32_t pe[2] = {1, 1};

        for (int t = blockIdx.x; t < G1_TILES; t += gridDim.x) {
            const int bm = (t >> 2) * 128;
            const int bn = (t & 3) * 256;
            const float* pA = x  + (size_t)(bm + r0) * D_DIM + c4 * 4;
            const float* pB = W1 + (size_t)(bn + r0) * D_DIM + c4 * 4;

            for (int i = 0; i < NIT; i++) {
                const int s = i & 1;
                const uint32_t mb_full  = sbase + 64 + 16 * s;
                const uint32_t mb_empty = mb_full + 8;
                mbar_wait(mb_empty, pe[s]); pe[s] ^= 1;

                const int k0 = i * BK;
                char* st = smem + 1024 + s * STAGE_BYTES;
#pragma unroll
                for (int j = 0; j < 4; j++) {
                    float4 v = *(const float4*)(pA + (size_t)(32 * j) * D_DIM + k0);
                    float4 h, l; split4(v, h, l);
                    *(float4*)(st + offA[j])           = h;
                    *(float4*)(st + OFF_ALO + offA[j]) = l;
                }
#pragma unroll
                for (int j = 0; j < 8; j++) {
                    float4 v = *(const float4*)(pB + (size_t)(32 * j) * D_DIM + k0);
                    float4 h, l; split4(v, h, l);
                    *(float4*)(st + OFF_BHI + offB[j]) = h;
                    *(float4*)(st + OFF_BLO + offB[j]) = l;
                }
                fence_proxy_async_cta();
                mbar_arrive(mb_full);
            }
        }
    } else if (tid == 256) {
        // ---------------- MMA issuer ----------------------------------------
        uint32_t pf[2] = {0, 0}, pd[2] = {0, 0};
        int lt = 0;
        for (int t = blockIdx.x; t < G1_TILES; t += gridDim.x) {
            const int b = lt & 1;
            if (lt >= 2) { mbar_wait(sbase + 96 + 16 * b + 8, pd[b]); pd[b] ^= 1; }
            const uint32_t dD = tmem_base + b * 256;

            for (int i = 0; i < NIT; i++) {
                const int s = i & 1;
                const uint32_t mb_full  = sbase + 64 + 16 * s;
                const uint32_t mb_empty = mb_full + 8;
                mbar_wait(mb_full, pf[s]); pf[s] ^= 1;

                uint32_t sb = sbase + 1024 + s * STAGE_BYTES;
                uint64_t dAh = make_desc_sw128(sb);
                uint64_t dAl = make_desc_sw128(sb + OFF_ALO);
                uint64_t dBh = make_desc_sw128(sb + OFF_BHI);
                uint64_t dBl = make_desc_sw128(sb + OFF_BLO);
#pragma unroll
                for (int ks = 0; ks < 4; ks++) {
                    mma_tf32_ss(dD, dAh + 2 * ks, dBh + 2 * ks, IDESC_G1,
                                (i == 0 && ks == 0) ? 0u : 1u);
                    mma_tf32_ss(dD, dAh + 2 * ks, dBl + 2 * ks, IDESC_G1, 1u);
                    mma_tf32_ss(dD, dAl + 2 * ks, dBh + 2 * ks, IDESC_G1, 1u);
                }
                tc_commit(mb_empty);
            }
            tc_commit(sbase + 96 + 16 * b);   // tile_done[b]
            lt++;
        }
    } else if (tid >= 288) {
        // ---------------- epilogue: 4 warps, 256 cols each -------------------
        const int sub = (tid >> 5) & 3;      // warps 9..12 -> subs 1,2,3,0
        const int lane = tid & 31;
        uint32_t pt[2] = {0, 0};
        int lt = 0;
        for (int t = blockIdx.x; t < G1_TILES; t += gridDim.x) {
            const int b = lt & 1;
            mbar_wait(sbase + 96 + 16 * b, pt[b]); pt[b] ^= 1;
            tc_fence_after();

            const int bm = (t >> 2) * 128;
            const int bn = (t & 3) * 256;
            const int row = bm + sub * 32 + lane;
            float* hrow = Hout + (size_t)row * H_DIM + bn;
            const float* brow = b1 + bn;
            const uint32_t dD = tmem_base + b * 256;
#pragma unroll
            for (int ch = 0; ch < 8; ch++) {
                uint32_t r[32];
                TC_LD_X32(r, dD + ch * 32);
                tc_wait_ld();
#pragma unroll
                for (int q = 0; q < 8; q++) {
                    float4 bias = *(const float4*)(brow + ch * 32 + q * 4);
                    float4 o;
                    o.x = gelu_erf(__uint_as_float(r[q * 4 + 0]) + bias.x);
                    o.y = gelu_erf(__uint_as_float(r[q * 4 + 1]) + bias.y);
                    o.z = gelu_erf(__uint_as_float(r[q * 4 + 2]) + bias.z);
                    o.w = gelu_erf(__uint_as_float(r[q * 4 + 3]) + bias.w);
                    *(float4*)(hrow + ch * 32 + q * 4) = o;
                }
            }
            tc_fence_before();
            mbar_arrive(sbase + 96 + 16 * b + 8);   // dfree[b]
            lt++;
        }
    }

    __syncthreads();
    if (tid >= 256 && tid < 288) tc_dealloc(tmem_base, 512);

#else  // ---------- FFMA fallback (generic pass; persistent) -----------------
    float* As = (float*)smem;
    float* Bs = As + 8 * 128;

    const int tx = tid & 15;
    const int ty = tid >> 4;
    const int lr = tid >> 1;
    const int lc = (tid & 1) * 4;

    for (int t = blockIdx.x; t < G1_TILES; t += gridDim.x) {
        const int bm = (t >> 2) * 128;
        for (int half = 0; half < 2; half++) {
            const int bn = (t & 3) * 256 + half * 128;
            float acc[8][8];
#pragma unroll
            for (int i = 0; i < 8; i++)
#pragma unroll
                for (int j = 0; j < 8; j++) acc[i][j] = 0.0f;

            for (int k0 = 0; k0 < D_DIM; k0 += 8) {
                __syncthreads();
                if (tid < 256) {
                    float4 a4 = *(const float4*)(x  + (size_t)(bm + lr) * D_DIM + lc + k0);
                    float4 b4 = *(const float4*)(W1 + (size_t)(bn + lr) * D_DIM + lc + k0);
                    As[(lc + 0) * 128 + lr] = a4.x; As[(lc + 1) * 128 + lr] = a4.y;
                    As[(lc + 2) * 128 + lr] = a4.z; As[(lc + 3) * 128 + lr] = a4.w;
                    Bs[(lc + 0) * 128 + lr] = b4.x; Bs[(lc + 1) * 128 + lr] = b4.y;
                    Bs[(lc + 2) * 128 + lr] = b4.z; Bs[(lc + 3) * 128 + lr] = b4.w;
                }
                __syncthreads();
                if (tid < 256) {
#pragma unroll
                    for (int kk = 0; kk < 8; kk++) {
                        float a[8], b[8];
                        *(float4*)(a)     = *(const float4*)&As[kk * 128 + ty * 8];
                        *(float4*)(a + 4) = *(const float4*)&As[kk * 128 + ty * 8 + 4];
                        *(float4*)(b)     = *(const float4*)&Bs[kk * 128 + tx * 8];
                        *(float4*)(b + 4) = *(const float4*)&Bs[kk * 128 + tx * 8 + 4];
#pragma unroll
                        for (int i = 0; i < 8; i++)
#pragma unroll
                            for (int j = 0; j < 8; j++)
                                acc[i][j] = fmaf(a[i], b[j], acc[i][j]);
                    }
                }
            }

            if (tid < 256) {
                float bias[8];
                *(float4*)(bias)     = *(const float4*)&b1[bn + tx * 8];
                *(float4*)(bias + 4) = *(const float4*)&b1[bn + tx * 8 + 4];
#pragma unroll
                for (int i = 0; i < 8; i++) {
                    const int row = bm + ty * 8 + i;
                    float o[8];
#pragma unroll
                    for (int j = 0; j < 8; j++)
                        o[j] = gelu_erf(acc[i][j] + bias[j]);
                    float* dst = Hout + (size_t)row * H_DIM + bn + tx * 8;
                    *(float4*)(dst)     = make_float4(o[0], o[1], o[2], o[3]);
                    *(float4*)(dst + 4) = make_float4(o[4], o[5], o[6], o[7]);
                }
            }
            __syncthreads();
        }
    }
#endif
}

// ============================================================================
// GEMM2: logits = (H @ W2^T + b2)/temp; top-2 softmax.  3xTF32, 4-stage pipe,
// in-register split (round-6 proven version). 288 threads.
// ============================================================================
#define NIT2 (H_DIM / 32)
#define STAGE2_BYTES 49152
#define OFF2_HLO 16384
#define OFF2_WHI 32768
#define OFF2_WLO 40960
#define GEMM2_SMEM (1024 + 4 * STAGE2_BYTES)

#define IDESC_G2 ((1u << 4) | (2u << 7) | (2u << 10) | ((64u / 8) << 17) | ((128u / 16) << 24))

extern "C" __global__ void __launch_bounds__(288, 1) gemm2_kernel(
    const float* __restrict__ Hin, const float* __restrict__ W2,
    const float* __restrict__ b2, const float* __restrict__ log_temp,
    float* __restrict__ out)
{
    extern __shared__ __align__(1024) char smem[];
    const int tid = threadIdx.x;
    const int bm = blockIdx.x * 128;

#if HAS_TCGEN05
    const uint32_t sbase = smem_u32(smem);

    if (tid == 0) {
#pragma unroll
        for (int s = 0; s < 4; s++) {
            mbar_init(sbase + 64 + 16 * s, 256);
            mbar_init(sbase + 64 + 16 * s + 8, 1);
        }
    }
    if (tid >= 256) tc_alloc(sbase, 64);
    __syncthreads();

    uint32_t tmem_base;
    asm volatile("ld.shared.b32 %0, [%1];" : "=r"(tmem_base) : "r"(sbase));

    if (tid < 256) {
        const int r0 = tid >> 3;
        const int c4 = tid & 7;
        uint32_t offH[4], offW[2];
#pragma unroll
        for (int j = 0; j < 4; j++)
            offH[j] = SWZ128((uint32_t)(r0 + 32 * j) * 128 + c4 * 16);
#pragma unroll
        for (int j = 0; j < 2; j++)
            offW[j] = SWZ128((uint32_t)(r0 + 32 * j) * 128 + c4 * 16);

        const float* pH = Hin + (size_t)(bm + r0) * H_DIM + c4 * 4;
        const float* pW = W2  + (size_t)r0 * H_DIM + c4 * 4;

        uint32_t pe[4] = {1, 1, 1, 1};

        for (int ii = 0; ii < NIT2 / 4; ii++) {
#pragma unroll
            for (int s = 0; s < 4; s++) {
                const int i = ii * 4 + s;
                const uint32_t mb_full  = sbase + 64 + 16 * s;
                const uint32_t mb_empty = mb_full + 8;
                mbar_wait(mb_empty, pe[s]); pe[s] ^= 1;

                const int k0 = i * 32;
                char* st = smem + 1024 + s * STAGE2_BYTES;
#pragma unroll
                for (int j = 0; j < 4; j++) {
                    float4 v = *(const float4*)(pH + (size_t)(32 * j) * H_DIM + k0);
                    float4 h, l; split4(v, h, l);
                    *(float4*)(st + offH[j])            = h;
                    *(float4*)(st + OFF2_HLO + offH[j]) = l;
                }
#pragma unroll
                for (int j = 0; j < 2; j++) {
                    float4 v = *(const float4*)(pW + (size_t)(32 * j) * H_DIM + k0);
                    float4 h, l; split4(v, h, l);
                    *(float4*)(st + OFF2_WHI + offW[j]) = h;
                    *(float4*)(st + OFF2_WLO + offW[j]) = l;
                }
                fence_proxy_async_cta();
                mbar_arrive(mb_full);
            }
        }

#pragma unroll
        for (int s = 0; s < 4; s++)
            mbar_wait(sbase + 64 + 16 * s + 8, pe[s]);
        tc_fence_after();
    } else if (tid == 256) {
        uint32_t pf[4] = {0, 0, 0, 0};
        for (int ii = 0; ii < NIT2 / 4; ii++) {
#pragma unroll
            for (int s = 0; s < 4; s++) {
                const int i = ii * 4 + s;
                const uint32_t mb_full  = sbase + 64 + 16 * s;
                const uint32_t mb_empty = mb_full + 8;
                mbar_wait(mb_full, pf[s]); pf[s] ^= 1;

                uint32_t sb = sbase + 1024 + s * STAGE2_BYTES;
                uint64_t dHh = make_desc_sw128(sb);
                uint64_t dHl = make_desc_sw128(sb + OFF2_HLO);
                uint64_t dWh = make_desc_sw128(sb + OFF2_WHI);
                uint64_t dWl = make_desc_sw128(sb + OFF2_WLO);
#pragma unroll
                for (int ks = 0; ks < 4; ks++) {
                    mma_tf32_ss(tmem_base, dHh + 2 * ks, dWh + 2 * ks, IDESC_G2,
                                (i == 0 && ks == 0) ? 0u : 1u);
                    mma_tf32_ss(tmem_base, dHh + 2 * ks, dWl + 2 * ks, IDESC_G2, 1u);
                    mma_tf32_ss(tmem_base, dHl + 2 * ks, dWh + 2 * ks, IDESC_G2, 1u);
                }
                tc_commit(mb_empty);
            }
        }
    }
    __syncthreads();

    float* Ls  = (float*)(smem + 1024);            // [128][65]
    float* p1s = (float*)(smem + 1024 + 33280);
    float* p2s = p1s + 128;
    int*   i1s = (int*)(p2s + 128);
    int*   i2s = i1s + 128;

    float t = expf(*log_temp);
    t = fminf(fmaxf(t, 1e-3f), 100.0f);
    const float it = 1.0f / t;

    if (tid < 256) {
        const int w = tid >> 5, lane = tid & 31;
        const int row = (w & 3) * 32 + lane;
        const int colbase = (w >> 2) * 32;
        uint32_t r[32];
        TC_LD_X32(r, tmem_base + colbase);
        tc_wait_ld();
#pragma unroll
        for (int c = 0; c < 32; c++)
            Ls[row * 65 + colbase + c] =
                (__uint_as_float(r[c]) + b2[colbase + c]) * it;
    }
    __syncthreads();

    if (tid < 128) {
        float m1 = -INFINITY, m2 = -INFINITY;
        int i1 = -1, i2 = -1;
#pragma unroll 8
        for (int e = 0; e < E_DIM; e++) {
            float v = Ls[tid * 65 + e];
            if (v > m1) { m2 = m1; i2 = i1; m1 = v; i1 = e; }
            else if (v > m2) { m2 = v; i2 = e; }
        }
        float ed = expf(m2 - m1);
        float s = 1.0f / (1.0f + ed);
        p1s[tid] = s;
        p2s[tid] = ed * s;
        i1s[tid] = i1;
        i2s[tid] = i2;
    }
    __syncthreads();

    if (tid < 256) {
        for (int idx = tid; idx < 128 * E_DIM; idx += 256) {
            const int r = idx >> 6;
            const int e = idx & 63;
            float v = 0.0f;
            if (e == i1s[r]) v = p1s[r];
            else if (e == i2s[r]) v = p2s[r];
            out[(size_t)(bm + r) * E_DIM + e] = v;
        }
    }

    __syncthreads();
    if (tid >= 256) tc_dealloc(tmem_base, 64);

#else  // ---------- FFMA fallback (generic pass) -----------------------------
    float* Hs  = (float*)smem;
    float* Ws  = Hs + 16 * 128;
    float* Ls  = Ws + 16 * 64;
    float* p1s = Ls + 128 * 65;
    float* p2s = p1s + 128;
    int*   i1s = (int*)(p2s + 128);
    int*   i2s = i1s + 128;

    const int tx = tid & 15;
    const int ty = tid >> 4;
    const int hr0 = tid >> 2;
    const int hc0 = (tid & 3) * 4;
    const int hr1 = (tid + 256) >> 2;
    const int wr = tid >> 2;
    const int wc = (tid & 3) * 4;

    float acc[8][4];
#pragma unroll
    for (int i = 0; i < 8; i++)
#pragma unroll
        for (int j = 0; j < 4; j++) acc[i][j] = 0.0f;

    for (int k0 = 0; k0 < H_DIM; k0 += 16) {
        __syncthreads();
        if (tid < 256) {
            float4 h0 = *(const float4*)(Hin + (size_t)(bm + hr0) * H_DIM + k0 + hc0);
            float4 h1 = *(const float4*)(Hin + (size_t)(bm + hr1) * H_DIM + k0 + hc0);
            float4 w4 = *(const float4*)(W2  + (size_t)wr * H_DIM + k0 + wc);
            Hs[(hc0 + 0) * 128 + hr0] = h0.x; Hs[(hc0 + 1) * 128 + hr0] = h0.y;
            Hs[(hc0 + 2) * 128 + hr0] = h0.z; Hs[(hc0 + 3) * 128 + hr0] = h0.w;
            Hs[(hc0 + 0) * 128 + hr1] = h1.x; Hs[(hc0 + 1) * 128 + hr1] = h1.y;
            Hs[(hc0 + 2) * 128 + hr1] = h1.z; Hs[(hc0 + 3) * 128 + hr1] = h1.w;
            Ws[(wc + 0) * 64 + wr] = w4.x; Ws[(wc + 1) * 64 + wr] = w4.y;
            Ws[(wc + 2) * 64 + wr] = w4.z; Ws[(wc + 3) * 64 + wr] = w4.w;
        }
        __syncthreads();
        if (tid < 256) {
#pragma unroll
            for (int kk = 0; kk < 16; kk++) {
                float a[8], b[4];
                *(float4*)(a)     = *(const float4*)&Hs[kk * 128 + ty * 8];
                *(float4*)(a + 4) = *(const float4*)&Hs[kk * 128 + ty * 8 + 4];
                *(float4*)(b)     = *(const float4*)&Ws[kk * 64 + tx * 4];
#pragma unroll
                for (int i = 0; i < 8; i++)
#pragma unroll
                    for (int j = 0; j < 4; j++)
                        acc[i][j] = fmaf(a[i], b[j], acc[i][j]);
            }
        }
    }

    float t = expf(*log_temp);
    t = fminf(fmaxf(t, 1e-3f), 100.0f);
    const float it = 1.0f / t;

    if (tid < 256) {
#pragma unroll
        for (int i = 0; i < 8; i++)
#pragma unroll
            for (int j = 0; j < 4; j++) {
                const int col = tx * 4 + j;
                Ls[(ty * 8 + i) * 65 + col] = (acc[i][j] + b2[col]) * it;
            }
    }
    __syncthreads();

    if (tid < 128) {
        float m1 = -INFINITY, m2 = -INFINITY;
        int i1 = -1, i2 = -1;
#pragma unroll 8
        for (int e = 0; e < E_DIM; e++) {
            float v = Ls[tid * 65 + e];
            if (v > m1) { m2 = m1; i2 = i1; m1 = v; i1 = e; }
            else if (v > m2) { m2 = v; i2 = e; }
        }
        float ed = expf(m2 - m1);
        float s = 1.0f / (1.0f + ed);
        p1s[tid] = s;
        p2s[tid] = ed * s;
        i1s[tid] = i1;
        i2s[tid] = i2;
    }
    __syncthreads();

    if (tid < 256) {
        for (int idx = tid; idx < 128 * E_DIM; idx += 256) {
            const int r = idx >> 6;
            const int e = idx & 63;
            float v = 0.0f;
            if (e == i1s[r]) v = p1s[r];
            else if (e == i2s[r]) v = p2s[r];
            out[(size_t)(bm + r) * E_DIM + e] = v;
        }
    }
#endif
}

// ---------------- launcher ---------------------------------------------------
extern "C" void kernel_launch(void* const* d_in, const int* in_sizes, int n_in,
                              void* d_out, int out_size) {
    const float* x  = (const float*)d_in[0];
    const float* W1 = (const float*)d_in[1];
    const float* b1 = (const float*)d_in[2];
    const float* W2 = (const float*)d_in[3];
    const float* b2 = (const float*)d_in[4];
    const float* lt = (const float*)d_in[5];
    float* out = (float*)d_out;

    const int M = in_sizes[0] / D_DIM;   // 65536

    float* Hbuf;
    cudaGetSymbolAddress((void**)&Hbuf, g_H);

    static int nsm = 0;
    if (!nsm) {
        cudaDeviceGetAttribute(&nsm, cudaDevAttrMultiProcessorCount, 0);
        cudaFuncSetAttribute(gemm1_kernel,
                             cudaFuncAttributeMaxDynamicSharedMemorySize, GEMM1_SMEM);
        cudaFuncSetAttribute(gemm2_kernel,
                             cudaFuncAttributeMaxDynamicSharedMemorySize, GEMM2_SMEM);
    }

    gemm1_kernel<<<nsm, 416, GEMM1_SMEM>>>(x, W1, b1, Hbuf);

    dim3 grid2(M / 128);
    gemm2_kernel<<<grid2, 288, GEMM2_SMEM>>>(Hbuf, W2, b2, lt, out);
}